// round 1
// baseline (speedup 1.0000x reference)
#include <cuda_runtime.h>
#include <math_constants.h>

#define KTOP 6      // K+1 with K=5
#define TPB  256

__device__ float g_row_loss[8192];

__device__ __forceinline__ void topk_insert(float (&t)[KTOP], float v) {
    // branchless sorted insert (descending); only called on rare path
    float x = v;
    #pragma unroll
    for (int j = 0; j < KTOP; ++j) {
        float hi = fmaxf(t[j], x);
        float lo = fminf(t[j], x);
        t[j] = hi;
        x = lo;
    }
}

__global__ __launch_bounds__(TPB) void autkc_row_kernel(
    const float* __restrict__ pred,
    const int*   __restrict__ y,
    int C)
{
    const int row = blockIdx.x;
    const float* __restrict__ p = pred + (long long)row * (long long)C;
    const int yi  = y[row];
    const int tid = threadIdx.x;

    float t[KTOP];
    #pragma unroll
    for (int j = 0; j < KTOP; ++j) t[j] = -CUDART_INF_F;
    float s = 0.0f;

    // ---- main streaming pass: sumexp + per-thread top-6 (excluding y) ----
    int col = tid;
    for (; col + 3 * TPB < C; col += 4 * TPB) {
        float v0 = p[col];
        float v1 = p[col +     TPB];
        float v2 = p[col + 2 * TPB];
        float v3 = p[col + 3 * TPB];
        s += __expf(v0) + __expf(v1) + __expf(v2) + __expf(v3);
        float m = fmaxf(fmaxf(v0, v1), fmaxf(v2, v3));
        if (m > t[KTOP - 1]) {                       // rare after warm-up
            if (v0 > t[KTOP - 1] && col           != yi) topk_insert(t, v0);
            if (v1 > t[KTOP - 1] && col +     TPB != yi) topk_insert(t, v1);
            if (v2 > t[KTOP - 1] && col + 2 * TPB != yi) topk_insert(t, v2);
            if (v3 > t[KTOP - 1] && col + 3 * TPB != yi) topk_insert(t, v3);
        }
    }
    for (; col < C; col += TPB) {
        float v = p[col];
        s += __expf(v);
        if (v > t[KTOP - 1] && col != yi) topk_insert(t, v);
    }

    // ---- block sum-reduce (deterministic tree) ----
    __shared__ float shsum[TPB / 32];
    #pragma unroll
    for (int o = 16; o > 0; o >>= 1) s += __shfl_down_sync(0xffffffffu, s, o);
    if ((tid & 31) == 0) shsum[tid >> 5] = s;

    // ---- block top-6 reduce: 6 masked argmax rounds over 256*6 candidates ----
    __shared__ float cand[TPB * KTOP];
    #pragma unroll
    for (int j = 0; j < KTOP; ++j) cand[tid + j * TPB] = t[j];

    __shared__ float wval[TPB / 32];
    __shared__ int   widx[TPB / 32];
    __shared__ float topv[KTOP];
    __syncthreads();

    float S_total = 0.0f;
    if (tid == 0) {
        #pragma unroll
        for (int w = 0; w < TPB / 32; ++w) S_total += shsum[w];
    }

    for (int r = 0; r < KTOP; ++r) {
        float bv = -CUDART_INF_F;
        int   bi = 0;
        #pragma unroll
        for (int j = 0; j < KTOP; ++j) {
            float v = cand[tid + j * TPB];
            if (v > bv) { bv = v; bi = tid + j * TPB; }
        }
        #pragma unroll
        for (int o = 16; o > 0; o >>= 1) {
            float ov = __shfl_down_sync(0xffffffffu, bv, o);
            int   oi = __shfl_down_sync(0xffffffffu, bi, o);
            if (ov > bv) { bv = ov; bi = oi; }
        }
        if ((tid & 31) == 0) { wval[tid >> 5] = bv; widx[tid >> 5] = bi; }
        __syncthreads();
        if (tid == 0) {
            float best = -CUDART_INF_F;
            int   besti = 0;
            #pragma unroll
            for (int w = 0; w < TPB / 32; ++w)
                if (wval[w] > best) { best = wval[w]; besti = widx[w]; }
            topv[r] = best;
            cand[besti] = -CUDART_INF_F;   // mask for next round
        }
        __syncthreads();
    }

    // ---- per-row loss ----
    if (tid == 0) {
        float invS = 1.0f / S_total;
        float py   = __expf(p[yi]) * invS;
        float acc  = 0.0f;
        #pragma unroll
        for (int r = 0; r < KTOP; ++r) {
            float pi = __expf(topv[r]) * invS;
            float d  = 1.0f + pi - py;
            acc += d * d;
        }
        g_row_loss[row] = acc * (1.0f / (float)(KTOP - 1));   // /K, K=5
    }
}

__global__ __launch_bounds__(TPB) void autkc_final_kernel(float* __restrict__ out, int B)
{
    __shared__ float shsum[TPB / 32];
    const int tid = threadIdx.x;
    float s = 0.0f;
    for (int i = tid; i < B; i += TPB) s += g_row_loss[i];
    #pragma unroll
    for (int o = 16; o > 0; o >>= 1) s += __shfl_down_sync(0xffffffffu, s, o);
    if ((tid & 31) == 0) shsum[tid >> 5] = s;
    __syncthreads();
    if (tid == 0) {
        float tot = 0.0f;
        #pragma unroll
        for (int w = 0; w < TPB / 32; ++w) tot += shsum[w];
        out[0] = tot / (float)B;
    }
}

extern "C" void kernel_launch(void* const* d_in, const int* in_sizes, int n_in,
                              void* d_out, int out_size)
{
    const float* pred = (const float*)d_in[0];
    const int*   y    = (const int*)d_in[1];
    // d_in[2] = epoch, unused (AUTKC branch is always taken for epoch >= 0)

    const int B = in_sizes[1];
    const int C = in_sizes[0] / B;

    autkc_row_kernel<<<B, TPB>>>(pred, y, C);
    autkc_final_kernel<<<1, TPB>>>((float*)d_out, B);
}

// round 2
// speedup vs baseline: 1.0481x; 1.0481x over previous
#include <cuda_runtime.h>
#include <math_constants.h>
#include <stdint.h>

#define KTOP 6      // K+1 with K=5
#define TPB  256

__device__ float g_row_loss[8192];
__device__ unsigned int g_ticket = 0;

__device__ __forceinline__ void topk_insert(float (&t)[KTOP], float v) {
    // branchless sorted insert (descending); only executed on rare path
    float x = v;
    #pragma unroll
    for (int j = 0; j < KTOP; ++j) {
        float hi = fmaxf(t[j], x);
        float lo = fminf(t[j], x);
        t[j] = hi;
        x = lo;
    }
}

__global__ __launch_bounds__(TPB) void autkc_fused_kernel(
    const float* __restrict__ pred,
    const int*   __restrict__ ylab,
    int C, int B,
    float* __restrict__ out)
{
    const int row = blockIdx.x;
    const float* __restrict__ p = pred + (long long)row * (long long)C;
    const int yi  = ylab[row];
    const int tid = threadIdx.x;

    float t[KTOP];
    #pragma unroll
    for (int j = 0; j < KTOP; ++j) t[j] = -CUDART_INF_F;
    float thr = -CUDART_INF_F;
    float s0 = 0.f, s1 = 0.f, s2 = 0.f, s3 = 0.f;

    // ---- alignment peel (row base may not be 16B aligned; C odd) ----
    const int mis  = (int)(((uintptr_t)p & 15u) >> 2);   // misaligned floats
    const int peel = (4 - mis) & 3;
    for (int i = tid; i < peel; i += TPB) {
        float v = p[i];
        s0 += __expf(v);
        if (v > thr && i != yi) { topk_insert(t, v); thr = t[KTOP - 1]; }
    }

    const int nvec = (C - peel) >> 2;
    const float4* __restrict__ pv = (const float4*)(p + peel);

    // ---- main streaming pass: 2x float4 per iteration ----
    int j = tid;
    for (; j + TPB < nvec; j += 2 * TPB) {
        float4 a = pv[j];
        float4 b = pv[j + TPB];
        s0 += __expf(a.x); s1 += __expf(a.y); s2 += __expf(a.z); s3 += __expf(a.w);
        s0 += __expf(b.x); s1 += __expf(b.y); s2 += __expf(b.z); s3 += __expf(b.w);
        float m = fmaxf(fmaxf(fmaxf(a.x, a.y), fmaxf(a.z, a.w)),
                        fmaxf(fmaxf(b.x, b.y), fmaxf(b.z, b.w)));
        if (m > thr) {                       // rare after warm-up
            int ba = peel + 4 * j;
            int bb = peel + 4 * (j + TPB);
            if (a.x > thr && ba + 0 != yi) topk_insert(t, a.x);
            if (a.y > thr && ba + 1 != yi) topk_insert(t, a.y);
            if (a.z > thr && ba + 2 != yi) topk_insert(t, a.z);
            if (a.w > thr && ba + 3 != yi) topk_insert(t, a.w);
            if (b.x > thr && bb + 0 != yi) topk_insert(t, b.x);
            if (b.y > thr && bb + 1 != yi) topk_insert(t, b.y);
            if (b.z > thr && bb + 2 != yi) topk_insert(t, b.z);
            if (b.w > thr && bb + 3 != yi) topk_insert(t, b.w);
            thr = t[KTOP - 1];
        }
    }
    for (; j < nvec; j += TPB) {
        float4 a = pv[j];
        s0 += __expf(a.x); s1 += __expf(a.y); s2 += __expf(a.z); s3 += __expf(a.w);
        float m = fmaxf(fmaxf(a.x, a.y), fmaxf(a.z, a.w));
        if (m > thr) {
            int ba = peel + 4 * j;
            if (a.x > thr && ba + 0 != yi) topk_insert(t, a.x);
            if (a.y > thr && ba + 1 != yi) topk_insert(t, a.y);
            if (a.z > thr && ba + 2 != yi) topk_insert(t, a.z);
            if (a.w > thr && ba + 3 != yi) topk_insert(t, a.w);
            thr = t[KTOP - 1];
        }
    }
    // scalar tail
    for (int i = peel + 4 * nvec + tid; i < C; i += TPB) {
        float v = p[i];
        s0 += __expf(v);
        if (v > thr && i != yi) { topk_insert(t, v); thr = t[KTOP - 1]; }
    }

    float s = (s0 + s1) + (s2 + s3);

    // ---- block sum-reduce (deterministic tree) ----
    __shared__ float shsum[TPB / 32];
    #pragma unroll
    for (int o = 16; o > 0; o >>= 1) s += __shfl_down_sync(0xffffffffu, s, o);
    if ((tid & 31) == 0) shsum[tid >> 5] = s;

    // ---- block top-6 reduce: 6 masked argmax rounds ----
    __shared__ float cand[TPB * KTOP];
    #pragma unroll
    for (int k = 0; k < KTOP; ++k) cand[tid + k * TPB] = t[k];

    __shared__ float wval[TPB / 32];
    __shared__ int   widx[TPB / 32];
    __shared__ float topv[KTOP];
    __syncthreads();

    float S_total = 0.0f;
    if (tid == 0) {
        #pragma unroll
        for (int w = 0; w < TPB / 32; ++w) S_total += shsum[w];
    }

    for (int r = 0; r < KTOP; ++r) {
        float bv = -CUDART_INF_F;
        int   bi = 0;
        #pragma unroll
        for (int k = 0; k < KTOP; ++k) {
            float v = cand[tid + k * TPB];
            if (v > bv) { bv = v; bi = tid + k * TPB; }
        }
        #pragma unroll
        for (int o = 16; o > 0; o >>= 1) {
            float ov = __shfl_down_sync(0xffffffffu, bv, o);
            int   oi = __shfl_down_sync(0xffffffffu, bi, o);
            if (ov > bv) { bv = ov; bi = oi; }
        }
        if ((tid & 31) == 0) { wval[tid >> 5] = bv; widx[tid >> 5] = bi; }
        __syncthreads();
        if (tid == 0) {
            float best = -CUDART_INF_F;
            int   besti = 0;
            #pragma unroll
            for (int w = 0; w < TPB / 32; ++w)
                if (wval[w] > best) { best = wval[w]; besti = widx[w]; }
            topv[r] = best;
            cand[besti] = -CUDART_INF_F;
        }
        __syncthreads();
    }

    // ---- per-row loss + last-CTA finalization ----
    __shared__ int is_last;
    if (tid == 0) {
        float invS = 1.0f / S_total;
        float py   = __expf(p[yi]) * invS;
        float acc  = 0.0f;
        #pragma unroll
        for (int r = 0; r < KTOP; ++r) {
            float pi = __expf(topv[r]) * invS;
            float d  = 1.0f + pi - py;
            acc += d * d;
        }
        g_row_loss[row] = acc * (1.0f / (float)(KTOP - 1));   // /K
        __threadfence();
        unsigned int done = atomicAdd(&g_ticket, 1u);
        is_last = (done == (unsigned int)(B - 1)) ? 1 : 0;
    }
    __syncthreads();

    if (is_last) {
        __threadfence();
        float fs = 0.0f;
        for (int i = tid; i < B; i += TPB) fs += g_row_loss[i];
        #pragma unroll
        for (int o = 16; o > 0; o >>= 1) fs += __shfl_down_sync(0xffffffffu, fs, o);
        __shared__ float fsh[TPB / 32];
        if ((tid & 31) == 0) fsh[tid >> 5] = fs;
        __syncthreads();
        if (tid == 0) {
            float tot = 0.0f;
            #pragma unroll
            for (int w = 0; w < TPB / 32; ++w) tot += fsh[w];
            out[0] = tot / (float)B;
            g_ticket = 0;   // reset for next graph replay
        }
    }
}

extern "C" void kernel_launch(void* const* d_in, const int* in_sizes, int n_in,
                              void* d_out, int out_size)
{
    const float* pred = (const float*)d_in[0];
    const int*   y    = (const int*)d_in[1];
    // d_in[2] = epoch, unused (AUTKC branch taken for epoch >= 0)

    const int B = in_sizes[1];
    const int C = in_sizes[0] / B;

    autkc_fused_kernel<<<B, TPB>>>(pred, y, C, B, (float*)d_out);
}

// round 3
// speedup vs baseline: 2.3215x; 2.2150x over previous
#include <cuda_runtime.h>
#include <math_constants.h>
#include <stdint.h>

#define KTOP 6       // K+1 with K=5
#define TPB  256
#define CAP  1536    // candidate buffer capacity (expected ~68 used)
#define THR  3.0f    // candidate threshold; guarded by exact fallback

__device__ float g_row_loss[8192];
__device__ unsigned int g_ticket = 0;

__device__ __forceinline__ void topk_insert(float (&t)[KTOP], float v) {
    float x = v;
    #pragma unroll
    for (int j = 0; j < KTOP; ++j) {
        float hi = fmaxf(t[j], x);
        float lo = fminf(t[j], x);
        t[j] = hi;
        x = lo;
    }
}

__global__ __launch_bounds__(TPB) void autkc_fused_kernel(
    const float* __restrict__ pred,
    const int*   __restrict__ ylab,
    int C, int B,
    float* __restrict__ out)
{
    const int row = blockIdx.x;
    const float* __restrict__ p = pred + (long long)row * (long long)C;
    const int yi  = ylab[row];
    const int tid = threadIdx.x;

    __shared__ float cval[CAP];
    __shared__ int   scnt;
    __shared__ float shsum[TPB / 32];
    __shared__ float wval[TPB / 32];
    __shared__ int   widx[TPB / 32];
    __shared__ float topv[KTOP];
    __shared__ int   is_last;

    if (tid == 0) scnt = 0;
    __syncthreads();

    float s0 = 0.f, s1 = 0.f, s2 = 0.f, s3 = 0.f;

    // ---- alignment peel (row base may not be 16B aligned; C odd) ----
    const int mis  = (int)(((uintptr_t)p & 15u) >> 2);
    const int peel = ((4 - mis) & 3);
    for (int i = tid; i < peel && i < C; i += TPB) {
        float v = p[i];
        s0 += __expf(v);
        if (v > THR && i != yi) {
            int pos = atomicAdd(&scnt, 1);
            if (pos < CAP) cval[pos] = v;
        }
    }

    const int nvec = (C - peel) >> 2;
    const float4* __restrict__ pv = (const float4*)(p + peel);

    // ---- hot streaming loop: sumexp + rare candidate push ----
    int j = tid;
    for (; j + TPB < nvec; j += 2 * TPB) {
        float4 a = pv[j];
        float4 b = pv[j + TPB];
        s0 += __expf(a.x); s1 += __expf(a.y); s2 += __expf(a.z); s3 += __expf(a.w);
        s0 += __expf(b.x); s1 += __expf(b.y); s2 += __expf(b.z); s3 += __expf(b.w);
        float m = fmaxf(fmaxf(fmaxf(a.x, a.y), fmaxf(a.z, a.w)),
                        fmaxf(fmaxf(b.x, b.y), fmaxf(b.z, b.w)));
        if (m > THR) {                          // ~1% of thread-iterations
            int ba = peel + 4 * j;
            int bb = peel + 4 * (j + TPB);
            float vv[8] = {a.x, a.y, a.z, a.w, b.x, b.y, b.z, b.w};
            int   ii[8] = {ba, ba + 1, ba + 2, ba + 3, bb, bb + 1, bb + 2, bb + 3};
            #pragma unroll
            for (int q = 0; q < 8; ++q) {
                if (vv[q] > THR && ii[q] != yi) {
                    int pos = atomicAdd(&scnt, 1);
                    if (pos < CAP) cval[pos] = vv[q];
                }
            }
        }
    }
    for (; j < nvec; j += TPB) {
        float4 a = pv[j];
        s0 += __expf(a.x); s1 += __expf(a.y); s2 += __expf(a.z); s3 += __expf(a.w);
        float m = fmaxf(fmaxf(a.x, a.y), fmaxf(a.z, a.w));
        if (m > THR) {
            int ba = peel + 4 * j;
            float vv[4] = {a.x, a.y, a.z, a.w};
            #pragma unroll
            for (int q = 0; q < 4; ++q) {
                if (vv[q] > THR && ba + q != yi) {
                    int pos = atomicAdd(&scnt, 1);
                    if (pos < CAP) cval[pos] = vv[q];
                }
            }
        }
    }
    for (int i = peel + 4 * nvec + tid; i < C; i += TPB) {
        float v = p[i];
        s0 += __expf(v);
        if (v > THR && i != yi) {
            int pos = atomicAdd(&scnt, 1);
            if (pos < CAP) cval[pos] = v;
        }
    }

    float s = (s0 + s1) + (s2 + s3);
    #pragma unroll
    for (int o = 16; o > 0; o >>= 1) s += __shfl_down_sync(0xffffffffu, s, o);
    if ((tid & 31) == 0) shsum[tid >> 5] = s;
    __syncthreads();

    // ---- candidate count check; exact fallback for adversarial input ----
    int n = scnt;
    if (n < KTOP || n > CAP) {
        // slow exact path: per-thread top-6 full rescan (never taken on normal data)
        float t[KTOP];
        #pragma unroll
        for (int k = 0; k < KTOP; ++k) t[k] = -CUDART_INF_F;
        float thr2 = -CUDART_INF_F;
        for (int i = tid; i < C; i += TPB) {
            float v = p[i];
            if (v > thr2 && i != yi) { topk_insert(t, v); thr2 = t[KTOP - 1]; }
        }
        __syncthreads();                 // everyone done reading old cval state
        #pragma unroll
        for (int k = 0; k < KTOP; ++k) cval[tid + k * TPB] = t[k];
        n = TPB * KTOP;
        __syncthreads();
    }

    // ---- top-6 of cval[0..n): 6 masked argmax rounds ----
    for (int r = 0; r < KTOP; ++r) {
        float bv = -CUDART_INF_F;
        int   bi = 0;
        for (int i = tid; i < n; i += TPB) {
            float v = cval[i];
            if (v > bv) { bv = v; bi = i; }
        }
        #pragma unroll
        for (int o = 16; o > 0; o >>= 1) {
            float ov = __shfl_down_sync(0xffffffffu, bv, o);
            int   oi = __shfl_down_sync(0xffffffffu, bi, o);
            if (ov > bv) { bv = ov; bi = oi; }
        }
        if ((tid & 31) == 0) { wval[tid >> 5] = bv; widx[tid >> 5] = bi; }
        __syncthreads();
        if (tid == 0) {
            float best = -CUDART_INF_F;
            int   besti = 0;
            #pragma unroll
            for (int w = 0; w < TPB / 32; ++w)
                if (wval[w] > best) { best = wval[w]; besti = widx[w]; }
            topv[r] = best;
            cval[besti] = -CUDART_INF_F;
        }
        __syncthreads();
    }

    // ---- per-row loss + fused last-CTA mean ----
    if (tid == 0) {
        float S_total = 0.0f;
        #pragma unroll
        for (int w = 0; w < TPB / 32; ++w) S_total += shsum[w];
        float invS = 1.0f / S_total;
        float py   = __expf(p[yi]) * invS;
        float acc  = 0.0f;
        #pragma unroll
        for (int r = 0; r < KTOP; ++r) {
            float pi = __expf(topv[r]) * invS;
            float d  = 1.0f + pi - py;
            acc += d * d;
        }
        g_row_loss[row] = acc * (1.0f / (float)(KTOP - 1));   // /K
        __threadfence();
        unsigned int done = atomicAdd(&g_ticket, 1u);
        is_last = (done == (unsigned int)(B - 1)) ? 1 : 0;
    }
    __syncthreads();

    if (is_last) {
        __threadfence();
        float fs = 0.0f;
        for (int i = tid; i < B; i += TPB) fs += g_row_loss[i];
        #pragma unroll
        for (int o = 16; o > 0; o >>= 1) fs += __shfl_down_sync(0xffffffffu, fs, o);
        if ((tid & 31) == 0) shsum[tid >> 5] = fs;
        __syncthreads();
        if (tid == 0) {
            float tot = 0.0f;
            #pragma unroll
            for (int w = 0; w < TPB / 32; ++w) tot += shsum[w];
            out[0] = tot / (float)B;
            g_ticket = 0;   // reset for next graph replay
        }
    }
}

extern "C" void kernel_launch(void* const* d_in, const int* in_sizes, int n_in,
                              void* d_out, int out_size)
{
    const float* pred = (const float*)d_in[0];
    const int*   y    = (const int*)d_in[1];
    // d_in[2] = epoch, unused (AUTKC branch taken for epoch >= 0)

    const int B = in_sizes[1];
    const int C = in_sizes[0] / B;

    autkc_fused_kernel<<<B, TPB>>>(pred, y, C, B, (float*)d_out);
}

// round 4
// speedup vs baseline: 2.3234x; 1.0008x over previous
#include <cuda_runtime.h>
#include <math_constants.h>
#include <stdint.h>

#define KTOP 6       // K+1 with K=5
#define TPB  128
#define CAP  1536    // candidate buffer capacity (expected ~68 used)
#define THR  3.0f    // candidate threshold; guarded by exact fallback

__device__ float g_row_loss[8192];
__device__ unsigned int g_ticket = 0;

__device__ __forceinline__ void topk_insert(float (&t)[KTOP], float v) {
    float x = v;
    #pragma unroll
    for (int j = 0; j < KTOP; ++j) {
        float hi = fmaxf(t[j], x);
        float lo = fminf(t[j], x);
        t[j] = hi;
        x = lo;
    }
}

__device__ __forceinline__ void push_cand(float v, int idx, int yi,
                                          int* scnt, float* cval) {
    if (v > THR && idx != yi) {
        int pos = atomicAdd(scnt, 1);
        if (pos < CAP) cval[pos] = v;
    }
}

__global__ __launch_bounds__(TPB) void autkc_fused_kernel(
    const float* __restrict__ pred,
    const int*   __restrict__ ylab,
    int C, int B,
    float* __restrict__ out)
{
    const int row = blockIdx.x;
    const float* __restrict__ p = pred + (long long)row * (long long)C;
    const int yi  = ylab[row];
    const int tid = threadIdx.x;

    __shared__ float cval[CAP];
    __shared__ int   scnt;
    __shared__ float shsum[TPB / 32];
    __shared__ float wval[TPB / 32];
    __shared__ int   widx[TPB / 32];
    __shared__ float topv[KTOP];
    __shared__ int   is_last;

    if (tid == 0) scnt = 0;
    __syncthreads();

    float s0 = 0.f, s1 = 0.f, s2 = 0.f, s3 = 0.f;

    // ---- alignment peel (row base may not be 16B aligned; C odd) ----
    const int mis  = (int)(((uintptr_t)p & 15u) >> 2);
    const int peel = ((4 - mis) & 3);
    for (int i = tid; i < peel && i < C; i += TPB) {
        float v = p[i];
        s0 += __expf(v);
        push_cand(v, i, yi, &scnt, cval);
    }

    const int nvec = (C - peel) >> 2;
    const float4* __restrict__ pv = (const float4*)(p + peel);

    // ---- hot streaming loop: 4x float4/iter, streaming loads ----
    int j = tid;
    for (; j + 3 * TPB < nvec; j += 4 * TPB) {
        float4 a = __ldcs(&pv[j]);
        float4 b = __ldcs(&pv[j +     TPB]);
        float4 c = __ldcs(&pv[j + 2 * TPB]);
        float4 d = __ldcs(&pv[j + 3 * TPB]);
        s0 += __expf(a.x); s1 += __expf(a.y); s2 += __expf(a.z); s3 += __expf(a.w);
        s0 += __expf(b.x); s1 += __expf(b.y); s2 += __expf(b.z); s3 += __expf(b.w);
        s0 += __expf(c.x); s1 += __expf(c.y); s2 += __expf(c.z); s3 += __expf(c.w);
        s0 += __expf(d.x); s1 += __expf(d.y); s2 += __expf(d.z); s3 += __expf(d.w);
        float m01 = fmaxf(fmaxf(fmaxf(a.x, a.y), fmaxf(a.z, a.w)),
                          fmaxf(fmaxf(b.x, b.y), fmaxf(b.z, b.w)));
        float m23 = fmaxf(fmaxf(fmaxf(c.x, c.y), fmaxf(c.z, c.w)),
                          fmaxf(fmaxf(d.x, d.y), fmaxf(d.z, d.w)));
        if (fmaxf(m01, m23) > THR) {            // rare (~2% of thread-iters)
            int ba = peel + 4 * j;
            push_cand(a.x, ba + 0,           yi, &scnt, cval);
            push_cand(a.y, ba + 1,           yi, &scnt, cval);
            push_cand(a.z, ba + 2,           yi, &scnt, cval);
            push_cand(a.w, ba + 3,           yi, &scnt, cval);
            int bb = ba + 4 * TPB;
            push_cand(b.x, bb + 0,           yi, &scnt, cval);
            push_cand(b.y, bb + 1,           yi, &scnt, cval);
            push_cand(b.z, bb + 2,           yi, &scnt, cval);
            push_cand(b.w, bb + 3,           yi, &scnt, cval);
            int bc = ba + 8 * TPB;
            push_cand(c.x, bc + 0,           yi, &scnt, cval);
            push_cand(c.y, bc + 1,           yi, &scnt, cval);
            push_cand(c.z, bc + 2,           yi, &scnt, cval);
            push_cand(c.w, bc + 3,           yi, &scnt, cval);
            int bd = ba + 12 * TPB;
            push_cand(d.x, bd + 0,           yi, &scnt, cval);
            push_cand(d.y, bd + 1,           yi, &scnt, cval);
            push_cand(d.z, bd + 2,           yi, &scnt, cval);
            push_cand(d.w, bd + 3,           yi, &scnt, cval);
        }
    }
    for (; j < nvec; j += TPB) {
        float4 a = __ldcs(&pv[j]);
        s0 += __expf(a.x); s1 += __expf(a.y); s2 += __expf(a.z); s3 += __expf(a.w);
        float m = fmaxf(fmaxf(a.x, a.y), fmaxf(a.z, a.w));
        if (m > THR) {
            int ba = peel + 4 * j;
            push_cand(a.x, ba + 0, yi, &scnt, cval);
            push_cand(a.y, ba + 1, yi, &scnt, cval);
            push_cand(a.z, ba + 2, yi, &scnt, cval);
            push_cand(a.w, ba + 3, yi, &scnt, cval);
        }
    }
    for (int i = peel + 4 * nvec + tid; i < C; i += TPB) {
        float v = p[i];
        s0 += __expf(v);
        push_cand(v, i, yi, &scnt, cval);
    }

    float s = (s0 + s1) + (s2 + s3);
    #pragma unroll
    for (int o = 16; o > 0; o >>= 1) s += __shfl_down_sync(0xffffffffu, s, o);
    if ((tid & 31) == 0) shsum[tid >> 5] = s;
    __syncthreads();

    // ---- candidate count check; exact fallback for adversarial input ----
    int n = scnt;
    if (n < KTOP || n > CAP) {
        float t[KTOP];
        #pragma unroll
        for (int k = 0; k < KTOP; ++k) t[k] = -CUDART_INF_F;
        float thr2 = -CUDART_INF_F;
        for (int i = tid; i < C; i += TPB) {
            float v = p[i];
            if (v > thr2 && i != yi) { topk_insert(t, v); thr2 = t[KTOP - 1]; }
        }
        __syncthreads();
        #pragma unroll
        for (int k = 0; k < KTOP; ++k) cval[tid + k * TPB] = t[k];
        n = TPB * KTOP;
        __syncthreads();
    }

    // ---- top-6 of cval[0..n): 6 masked argmax rounds ----
    for (int r = 0; r < KTOP; ++r) {
        float bv = -CUDART_INF_F;
        int   bi = 0;
        for (int i = tid; i < n; i += TPB) {
            float v = cval[i];
            if (v > bv) { bv = v; bi = i; }
        }
        #pragma unroll
        for (int o = 16; o > 0; o >>= 1) {
            float ov = __shfl_down_sync(0xffffffffu, bv, o);
            int   oi = __shfl_down_sync(0xffffffffu, bi, o);
            if (ov > bv) { bv = ov; bi = oi; }
        }
        if ((tid & 31) == 0) { wval[tid >> 5] = bv; widx[tid >> 5] = bi; }
        __syncthreads();
        if (tid == 0) {
            float best = -CUDART_INF_F;
            int   besti = 0;
            #pragma unroll
            for (int w = 0; w < TPB / 32; ++w)
                if (wval[w] > best) { best = wval[w]; besti = widx[w]; }
            topv[r] = best;
            cval[besti] = -CUDART_INF_F;
        }
        __syncthreads();
    }

    // ---- per-row loss + fused last-CTA mean ----
    if (tid == 0) {
        float S_total = 0.0f;
        #pragma unroll
        for (int w = 0; w < TPB / 32; ++w) S_total += shsum[w];
        float invS = 1.0f / S_total;
        float py   = __expf(p[yi]) * invS;
        float acc  = 0.0f;
        #pragma unroll
        for (int r = 0; r < KTOP; ++r) {
            float pi = __expf(topv[r]) * invS;
            float dd = 1.0f + pi - py;
            acc += dd * dd;
        }
        g_row_loss[row] = acc * (1.0f / (float)(KTOP - 1));   // /K
        __threadfence();
        unsigned int done = atomicAdd(&g_ticket, 1u);
        is_last = (done == (unsigned int)(B - 1)) ? 1 : 0;
    }
    __syncthreads();

    if (is_last) {
        __threadfence();
        float fs = 0.0f;
        for (int i = tid; i < B; i += TPB) fs += g_row_loss[i];
        #pragma unroll
        for (int o = 16; o > 0; o >>= 1) fs += __shfl_down_sync(0xffffffffu, fs, o);
        if ((tid & 31) == 0) shsum[tid >> 5] = fs;
        __syncthreads();
        if (tid == 0) {
            float tot = 0.0f;
            #pragma unroll
            for (int w = 0; w < TPB / 32; ++w) tot += shsum[w];
            out[0] = tot / (float)B;
            g_ticket = 0;   // reset for next graph replay
        }
    }
}

extern "C" void kernel_launch(void* const* d_in, const int* in_sizes, int n_in,
                              void* d_out, int out_size)
{
    const float* pred = (const float*)d_in[0];
    const int*   y    = (const int*)d_in[1];
    // d_in[2] = epoch, unused (AUTKC branch taken for epoch >= 0)

    const int B = in_sizes[1];
    const int C = in_sizes[0] / B;

    autkc_fused_kernel<<<B, TPB>>>(pred, y, C, B, (float*)d_out);
}